// round 6
// baseline (speedup 1.0000x reference)
#include <cuda_runtime.h>
#include <cstdint>
#define BB 16
#define TT 128
#define HH 512
#define G4 2048
#define BTV (BB*TT*VV)
#define VV 32000
#define WPAD 516
typedef unsigned long long ull;

__device__ float g_X [TT*BB*HH];
__device__ float g_GX[TT*BB*G4];
__device__ float g_HS[TT*BB*HH];
__device__ float g_h [BB*HH];
__device__ float g_bias[G4];
__device__ unsigned g_bar[2];
__device__ int g_tok_is64;

__device__ __forceinline__ ull pack2(float x, float y){ull r;asm("mov.b64 %0,{%1,%2};":"=l"(r):"f"(x),"f"(y));return r;}
__device__ __forceinline__ float2 unpack2(ull v){float2 r;asm("mov.b64 {%0,%1},%2;":"=f"(r.x),"=f"(r.y):"l"(v));return r;}
__device__ __forceinline__ ull fma2(ull a,ull b,ull c){ull d;asm("fma.rn.f32x2 %0,%1,%2,%3;":"=l"(d):"l"(a),"l"(b),"l"(c));return d;}

__global__ void detect_tok_kernel(const unsigned* __restrict__ w){
    __shared__ int any;
    if(threadIdx.x==0) any=0;
    __syncthreads();
    int a=0;
    for(int i=threadIdx.x;i<1024;i+=blockDim.x) a|=(w[2*i+1]!=0u);
    if(a) atomicOr(&any,1);
    __syncthreads();
    if(threadIdx.x==0) g_tok_is64=(any==0)?1:0;
}

__global__ void prep_bias_kernel(const float* __restrict__ bi,const float* __restrict__ bh){
    int i=blockIdx.x*blockDim.x+threadIdx.x;
    if(i<G4) g_bias[i]=bi[i]+bh[i];
    if(i==0){ g_bar[0]=0u; g_bar[1]=0u; }
}

__global__ void embed_relu_kernel(const void* __restrict__ tgt,const float* __restrict__ emb){
    int m=blockIdx.x, t=m>>4, b=m&15;
    long long tok;
    if(t==0) tok=1LL;
    else if(g_tok_is64) tok=((const long long*)tgt)[b*TT+(t-1)];
    else tok=(long long)((const int*)tgt)[b*TT+(t-1)];
    const float4* src=(const float4*)(emb+(size_t)tok*HH);
    float4* dst=(float4*)(g_X+(size_t)m*HH);
    float4 v=__ldg(src+threadIdx.x);
    v.x=fmaxf(v.x,0.f); v.y=fmaxf(v.y,0.f); v.z=fmaxf(v.z,0.f); v.w=fmaxf(v.w,0.f);
    dst[threadIdx.x]=v;
}

// C[M,N] = A[M,512] @ Bw[N,512]^T + bias[N].  BM=BN=128, BK=16, 256 thr, 8x8/thr.
// MODE0: C=g_GX ldc=2048.  MODE1: row m=t*16+b -> out row b*128+t, ldc=32000.
template<int MODE>
__global__ __launch_bounds__(256,2)
void sgemm_kernel(const float* __restrict__ A,const float* __restrict__ Bw,
                  const float* __restrict__ bias,float* __restrict__ C){
    __shared__ float As[2][16][128];
    __shared__ float Bs[2][16][128];
    const int tid=threadIdx.x, tx=tid&15, ty=tid>>4;
    const int row0=blockIdx.y*128, col0=blockIdx.x*128, q0=tid*2;
    float4 ra[2], rb[2];
    ull acc[8][4];
    #pragma unroll
    for(int mi=0;mi<8;mi++)
        #pragma unroll
        for(int j=0;j<4;j++) acc[mi][j]=0ULL;
    auto loadT=[&](int kt){
        #pragma unroll
        for(int i=0;i<2;i++){
            int q=q0+i, r=q>>2, k4=q&3;
            ra[i]=__ldg((const float4*)(A +(size_t)(row0+r)*512+kt*16+k4*4));
            rb[i]=__ldg((const float4*)(Bw+(size_t)(col0+r)*512+kt*16+k4*4));
        }
    };
    auto storeT=[&](int s){
        #pragma unroll
        for(int i=0;i<2;i++){
            int q=q0+i, r=q>>2, kk=(q&3)*4;
            As[s][kk+0][r]=ra[i].x; As[s][kk+1][r]=ra[i].y;
            As[s][kk+2][r]=ra[i].z; As[s][kk+3][r]=ra[i].w;
            Bs[s][kk+0][r]=rb[i].x; Bs[s][kk+1][r]=rb[i].y;
            Bs[s][kk+2][r]=rb[i].z; Bs[s][kk+3][r]=rb[i].w;
        }
    };
    loadT(0); storeT(0); __syncthreads();
    int s=0;
    for(int kt=0;kt<32;kt++){
        if(kt<31) loadT(kt+1);
        #pragma unroll
        for(int k=0;k<16;k++){
            float4 a0=*(const float4*)&As[s][k][ty*4];
            float4 a1=*(const float4*)&As[s][k][64+ty*4];
            float4 b0=*(const float4*)&Bs[s][k][tx*4];
            float4 b1=*(const float4*)&Bs[s][k][64+tx*4];
            ull bb[4]={pack2(b0.x,b0.y),pack2(b0.z,b0.w),pack2(b1.x,b1.y),pack2(b1.z,b1.w)};
            float av[8]={a0.x,a0.y,a0.z,a0.w,a1.x,a1.y,a1.z,a1.w};
            #pragma unroll
            for(int mi=0;mi<8;mi++){
                ull pa=pack2(av[mi],av[mi]);
                #pragma unroll
                for(int j=0;j<4;j++) acc[mi][j]=fma2(pa,bb[j],acc[mi][j]);
            }
        }
        if(kt<31) storeT(s^1);
        __syncthreads();
        s^=1;
    }
    const int n0=col0+tx*4, n1=col0+64+tx*4;
    float4 bs0=__ldg((const float4*)&bias[n0]);
    float4 bs1=__ldg((const float4*)&bias[n1]);
    #pragma unroll
    for(int mi=0;mi<8;mi++){
        int gm=row0+((mi<4)?(ty*4+mi):(64+ty*4+mi-4));
        size_t ro;
        if(MODE==0) ro=(size_t)gm*2048;
        else { int b=gm&15, t=gm>>4; ro=(size_t)(b*128+t)*32000; }
        float2 p0=unpack2(acc[mi][0]),p1=unpack2(acc[mi][1]);
        float2 p2=unpack2(acc[mi][2]),p3=unpack2(acc[mi][3]);
        *(float4*)(C+ro+n0)=make_float4(p0.x+bs0.x,p0.y+bs0.y,p1.x+bs0.z,p1.y+bs0.w);
        *(float4*)(C+ro+n1)=make_float4(p2.x+bs1.x,p2.y+bs1.y,p3.x+bs1.z,p3.y+bs1.w);
    }
}

// persistent LSTM recurrence: 128 CTAs x 256 thr, CTA owns 4 hidden units.
__global__ __launch_bounds__(256,1)
void recurrence_kernel(const float* __restrict__ W_hh,const float* __restrict__ h0,
                       const float* __restrict__ c0,float* __restrict__ out_tail){
    extern __shared__ float sm[];
    float* Ws=sm;              // 16*516
    float* hb=sm+8256;         // 16*516
    float* part=sm+16512;      // 256*17
    float* gs=sm+20864;        // 256
    float* cs=sm+21120;        // 64
    const int tid=threadIdx.x, cta=blockIdx.x, u0=cta*4;
    #pragma unroll
    for(int i=0;i<8;i++){
        int q=i*256+tid, r=q>>7, kq=q&127;
        int jr=(r>>2)*512+u0+(r&3);
        float4 w=__ldg((const float4*)W_hh+(size_t)jr*128+kq);
        *(float4*)&Ws[r*WPAD+kq*4]=w;
    }
    if(tid<64){ int uu=tid>>4,b=tid&15; cs[uu*16+b]=c0[b*HH+u0+uu]; }
    __syncthreads();
    const int rq=tid&3, bq=(tid>>2)&3, ks=tid>>4, k0=ks*32;
    for(int t=0;t<TT;t++){
        const float4* hs4=(t==0)?(const float4*)h0:(const float4*)g_h;
        #pragma unroll
        for(int i=0;i<8;i++){
            int q=i*256+tid, b=q>>7, kq=q&127;
            float4 v=__ldcg(hs4+q);
            *(float4*)&hb[b*WPAD+kq*4]=v;
        }
        __syncthreads();
        float acc[4][4];
        #pragma unroll
        for(int i=0;i<4;i++)
            #pragma unroll
            for(int j=0;j<4;j++) acc[i][j]=0.f;
        const float* wb=&Ws[(4*rq)*WPAD+k0];
        const float* hbb=&hb[(4*bq)*WPAD+k0];
        #pragma unroll
        for(int kk=0;kk<32;kk+=4){
            float4 w4[4],h4[4];
            #pragma unroll
            for(int i=0;i<4;i++) w4[i]=*(const float4*)(wb+i*WPAD+kk);
            #pragma unroll
            for(int j=0;j<4;j++) h4[j]=*(const float4*)(hbb+j*WPAD+kk);
            #pragma unroll
            for(int i=0;i<4;i++)
                #pragma unroll
                for(int j=0;j<4;j++)
                    acc[i][j]+=w4[i].x*h4[j].x+w4[i].y*h4[j].y+w4[i].z*h4[j].z+w4[i].w*h4[j].w;
        }
        #pragma unroll
        for(int i=0;i<4;i++)
            #pragma unroll
            for(int j=0;j<4;j++)
                part[((4*rq+i)*16+(4*bq+j))*17+ks]=acc[i][j];
        __syncthreads();
        {
            float ssum=0.f;
            #pragma unroll
            for(int k2=0;k2<16;k2++) ssum+=part[tid*17+k2];
            int r=tid>>4,b=tid&15;
            int jg=(r>>2)*512+u0+(r&3);
            gs[tid]=ssum+__ldg(&g_GX[(size_t)(t*16+b)*2048+jg]);
        }
        __syncthreads();
        if(tid<64){
            int uu=tid>>4,b=tid&15;
            float xi=gs[(0+uu)*16+b], xf=gs[(4+uu)*16+b];
            float xg=gs[(8+uu)*16+b], xo=gs[(12+uu)*16+b];
            float c=cs[uu*16+b];
            float si=1.f/(1.f+expf(-xi)), sf=1.f/(1.f+expf(-xf)), so=1.f/(1.f+expf(-xo));
            float c2=sf*c+si*tanhf(xg);
            float h2=so*tanhf(c2);
            cs[uu*16+b]=c2;
            int unit=u0+uu;
            g_h[b*HH+unit]=h2;
            g_HS[(size_t)(t*16+b)*HH+unit]=h2;
            if(t==TT-1){ out_tail[b*HH+unit]=h2; out_tail[BB*HH+b*HH+unit]=c2; }
        }
        if(t<TT-1){
            __syncthreads();
            if(tid==0){
                __threadfence();
                unsigned a=atomicAdd(&g_bar[0],1u);
                if(a==127u){ atomicExch(&g_bar[0],0u); __threadfence(); atomicAdd(&g_bar[1],1u); }
                else { while(((volatile unsigned*)g_bar)[1]<(unsigned)(t+1)) __nanosleep(40); }
                __threadfence();
            }
            __syncthreads();
        }
    }
}

extern "C" void kernel_launch(void* const* d_in,const int* in_sizes,int n_in,
                              void* d_out,int out_size){
    const float* h0   =(const float*)d_in[1];
    const float* c0   =(const float*)d_in[2];
    const void*  tgt  =d_in[3];
    const float* emb  =(const float*)d_in[4];
    const float* W_ih =(const float*)d_in[5];
    const float* W_hh =(const float*)d_in[6];
    const float* b_ih =(const float*)d_in[7];
    const float* b_hh =(const float*)d_in[8];
    const float* W_out=(const float*)d_in[9];
    const float* b_out=(const float*)d_in[10];
    float* out=(float*)d_out;
    void *Xp,*GXp,*HSp,*biasp;
    cudaGetSymbolAddress(&Xp,g_X);
    cudaGetSymbolAddress(&GXp,g_GX);
    cudaGetSymbolAddress(&HSp,g_HS);
    cudaGetSymbolAddress(&biasp,g_bias);
    const int rec_smem=21184*4;
    cudaFuncSetAttribute(recurrence_kernel,cudaFuncAttributeMaxDynamicSharedMemorySize,rec_smem);
    detect_tok_kernel<<<1,256>>>((const unsigned*)tgt);
    prep_bias_kernel<<<G4/256,256>>>(b_ih,b_hh);
    embed_relu_kernel<<<TT*BB,128>>>(tgt,emb);
    sgemm_kernel<0><<<dim3(16,16),256>>>((const float*)Xp,W_ih,(const float*)biasp,(float*)GXp);
    recurrence_kernel<<<128,256,rec_smem>>>(W_hh,h0,c0,out+BTV);
    sgemm_kernel<1><<<dim3(250,16),256>>>((const float*)HSp,W_out,b_out,out);
}

// round 10
// speedup vs baseline: 1.7081x; 1.7081x over previous
#include <cuda_runtime.h>
#include <cuda_fp16.h>
#include <cstdint>
#define BB 16
#define TT 128
#define HH 512
#define G4 2048
#define VV 32000
#define BTV (BB*TT*VV)
#define WPAD 516
typedef unsigned long long ull;
typedef unsigned short ushortt;

__device__ float g_X [TT*BB*HH];
__device__ float g_GX[TT*BB*G4];
__device__ float g_HS[TT*BB*HH];
__device__ float g_h [BB*HH];
__device__ float g_bias[G4];
__device__ unsigned g_bar[2];
__device__ int g_tok_is64;
__device__ ushortt g_A16[(size_t)2048*512];
__device__ ushortt g_B16[(size_t)VV*512];

__device__ __forceinline__ ull pack2(float x, float y){ull r;asm("mov.b64 %0,{%1,%2};":"=l"(r):"f"(x),"f"(y));return r;}
__device__ __forceinline__ float2 unpack2(ull v){float2 r;asm("mov.b64 {%0,%1},%2;":"=f"(r.x),"=f"(r.y):"l"(v));return r;}
__device__ __forceinline__ ull fma2(ull a,ull b,ull c){ull d;asm("fma.rn.f32x2 %0,%1,%2,%3;":"=l"(d):"l"(a),"l"(b),"l"(c));return d;}
__device__ __forceinline__ uint32_t s2u(const void* p){
    uint32_t a; asm("{ .reg .u64 t; cvta.to.shared.u64 t,%1; cvt.u32.u64 %0,t; }":"=r"(a):"l"(p)); return a;
}

__global__ void detect_tok_kernel(const unsigned* __restrict__ w){
    __shared__ int any;
    if(threadIdx.x==0) any=0;
    __syncthreads();
    int a=0;
    for(int i=threadIdx.x;i<1024;i+=blockDim.x) a|=(w[2*i+1]!=0u);
    if(a) atomicOr(&any,1);
    __syncthreads();
    if(threadIdx.x==0) g_tok_is64=(any==0)?1:0;
}

__global__ void prep_bias_kernel(const float* __restrict__ bi,const float* __restrict__ bh){
    int i=blockIdx.x*blockDim.x+threadIdx.x;
    if(i<G4) g_bias[i]=bi[i]+bh[i];
    if(i==0){ g_bar[0]=0u; g_bar[1]=0u; }
}

__global__ void embed_relu_kernel(const void* __restrict__ tgt,const float* __restrict__ emb){
    int m=blockIdx.x, t=m>>4, b=m&15;
    long long tok;
    if(t==0) tok=1LL;
    else if(g_tok_is64) tok=((const long long*)tgt)[b*TT+(t-1)];
    else tok=(long long)((const int*)tgt)[b*TT+(t-1)];
    const float4* src=(const float4*)(emb+(size_t)tok*HH);
    float4* dst=(float4*)(g_X+(size_t)m*HH);
    float4 v=__ldg(src+threadIdx.x);
    v.x=fmaxf(v.x,0.f); v.y=fmaxf(v.y,0.f); v.z=fmaxf(v.z,0.f); v.w=fmaxf(v.w,0.f);
    dst[threadIdx.x]=v;
}

// ---- fp16 conversions ----
__device__ __forceinline__ ull pack4h(float4 v){
    ushortt a=__half_as_ushort(__float2half_rn(v.x));
    ushortt b=__half_as_ushort(__float2half_rn(v.y));
    ushortt c=__half_as_ushort(__float2half_rn(v.z));
    ushortt d=__half_as_ushort(__float2half_rn(v.w));
    return (ull)a|((ull)b<<16)|((ull)c<<32)|((ull)d<<48);
}
__global__ void convB_kernel(const float* __restrict__ W){
    size_t i=(size_t)blockIdx.x*blockDim.x+threadIdx.x;
    if(i>=(size_t)VV*128) return;
    float4 v=__ldg((const float4*)W + i);
    ((ull*)g_B16)[i]=pack4h(v);
}
__global__ void convA_kernel(){
    size_t i=(size_t)blockIdx.x*blockDim.x+threadIdx.x;
    if(i>=(size_t)2048*128) return;
    float4 v=*((const float4*)g_HS + i);
    ((ull*)g_A16)[i]=pack4h(v);
}

// C[M,N] = A[M,512] @ Bw[N,512]^T + bias[N]. fp32, used for GX only.
__global__ __launch_bounds__(256,2)
void sgemm_kernel(const float* __restrict__ A,const float* __restrict__ Bw,
                  const float* __restrict__ bias,float* __restrict__ C){
    __shared__ float As[2][16][128];
    __shared__ float Bs[2][16][128];
    const int tid=threadIdx.x, tx=tid&15, ty=tid>>4;
    const int row0=blockIdx.y*128, col0=blockIdx.x*128, q0=tid*2;
    float4 ra[2], rb[2];
    ull acc[8][4];
    #pragma unroll
    for(int mi=0;mi<8;mi++)
        #pragma unroll
        for(int j=0;j<4;j++) acc[mi][j]=0ULL;
    auto loadT=[&](int kt){
        #pragma unroll
        for(int i=0;i<2;i++){
            int q=q0+i, r=q>>2, k4=q&3;
            ra[i]=__ldg((const float4*)(A +(size_t)(row0+r)*512+kt*16+k4*4));
            rb[i]=__ldg((const float4*)(Bw+(size_t)(col0+r)*512+kt*16+k4*4));
        }
    };
    auto storeT=[&](int s){
        #pragma unroll
        for(int i=0;i<2;i++){
            int q=q0+i, r=q>>2, kk=(q&3)*4;
            As[s][kk+0][r]=ra[i].x; As[s][kk+1][r]=ra[i].y;
            As[s][kk+2][r]=ra[i].z; As[s][kk+3][r]=ra[i].w;
            Bs[s][kk+0][r]=rb[i].x; Bs[s][kk+1][r]=rb[i].y;
            Bs[s][kk+2][r]=rb[i].z; Bs[s][kk+3][r]=rb[i].w;
        }
    };
    loadT(0); storeT(0); __syncthreads();
    int s=0;
    for(int kt=0;kt<32;kt++){
        if(kt<31) loadT(kt+1);
        #pragma unroll
        for(int k=0;k<16;k++){
            float4 a0=*(const float4*)&As[s][k][ty*4];
            float4 a1=*(const float4*)&As[s][k][64+ty*4];
            float4 b0=*(const float4*)&Bs[s][k][tx*4];
            float4 b1=*(const float4*)&Bs[s][k][64+tx*4];
            ull bb[4]={pack2(b0.x,b0.y),pack2(b0.z,b0.w),pack2(b1.x,b1.y),pack2(b1.z,b1.w)};
            float av[8]={a0.x,a0.y,a0.z,a0.w,a1.x,a1.y,a1.z,a1.w};
            #pragma unroll
            for(int mi=0;mi<8;mi++){
                ull pa=pack2(av[mi],av[mi]);
                #pragma unroll
                for(int j=0;j<4;j++) acc[mi][j]=fma2(pa,bb[j],acc[mi][j]);
            }
        }
        if(kt<31) storeT(s^1);
        __syncthreads();
        s^=1;
    }
    const int n0=col0+tx*4, n1=col0+64+tx*4;
    float4 bs0=__ldg((const float4*)&bias[n0]);
    float4 bs1=__ldg((const float4*)&bias[n1]);
    #pragma unroll
    for(int mi=0;mi<8;mi++){
        int gm=row0+((mi<4)?(ty*4+mi):(64+ty*4+mi-4));
        size_t ro=(size_t)gm*2048;
        float2 p0=unpack2(acc[mi][0]),p1=unpack2(acc[mi][1]);
        float2 p2=unpack2(acc[mi][2]),p3=unpack2(acc[mi][3]);
        *(float4*)(C+ro+n0)=make_float4(p0.x+bs0.x,p0.y+bs0.y,p1.x+bs0.z,p1.y+bs0.w);
        *(float4*)(C+ro+n1)=make_float4(p2.x+bs1.x,p2.y+bs1.y,p3.x+bs1.z,p3.y+bs1.w);
    }
}

// persistent LSTM recurrence: 128 CTAs x 256 thr, CTA owns 4 hidden units.
__global__ __launch_bounds__(256,1)
void recurrence_kernel(const float* __restrict__ W_hh,const float* __restrict__ h0,
                       const float* __restrict__ c0,float* __restrict__ out_tail){
    extern __shared__ float sm[];
    float* Ws=sm;
    float* hb=sm+8256;
    float* part=sm+16512;
    float* gs=sm+20864;
    float* cs=sm+21120;
    const int tid=threadIdx.x, cta=blockIdx.x, u0=cta*4;
    #pragma unroll
    for(int i=0;i<8;i++){
        int q=i*256+tid, r=q>>7, kq=q&127;
        int jr=(r>>2)*512+u0+(r&3);
        float4 w=__ldg((const float4*)W_hh+(size_t)jr*128+kq);
        *(float4*)&Ws[r*WPAD+kq*4]=w;
    }
    if(tid<64){ int uu=tid>>4,b=tid&15; cs[uu*16+b]=c0[b*HH+u0+uu]; }
    __syncthreads();
    const int rq=tid&3, bq=(tid>>2)&3, ks=tid>>4, k0=ks*32;
    for(int t=0;t<TT;t++){
        const float4* hs4=(t==0)?(const float4*)h0:(const float4*)g_h;
        #pragma unroll
        for(int i=0;i<8;i++){
            int q=i*256+tid, b=q>>7, kq=q&127;
            float4 v=__ldcg(hs4+q);
            *(float4*)&hb[b*WPAD+kq*4]=v;
        }
        __syncthreads();
        float acc[4][4];
        #pragma unroll
        for(int i=0;i<4;i++)
            #pragma unroll
            for(int j=0;j<4;j++) acc[i][j]=0.f;
        const float* wb=&Ws[(4*rq)*WPAD+k0];
        const float* hbb=&hb[(4*bq)*WPAD+k0];
        #pragma unroll
        for(int kk=0;kk<32;kk+=4){
            float4 w4[4],h4[4];
            #pragma unroll
            for(int i=0;i<4;i++) w4[i]=*(const float4*)(wb+i*WPAD+kk);
            #pragma unroll
            for(int j=0;j<4;j++) h4[j]=*(const float4*)(hbb+j*WPAD+kk);
            #pragma unroll
            for(int i=0;i<4;i++)
                #pragma unroll
                for(int j=0;j<4;j++)
                    acc[i][j]+=w4[i].x*h4[j].x+w4[i].y*h4[j].y+w4[i].z*h4[j].z+w4[i].w*h4[j].w;
        }
        #pragma unroll
        for(int i=0;i<4;i++)
            #pragma unroll
            for(int j=0;j<4;j++)
                part[((4*rq+i)*16+(4*bq+j))*17+ks]=acc[i][j];
        __syncthreads();
        {
            float ssum=0.f;
            #pragma unroll
            for(int k2=0;k2<16;k2++) ssum+=part[tid*17+k2];
            int r=tid>>4,b=tid&15;
            int jg=(r>>2)*512+u0+(r&3);
            gs[tid]=ssum+__ldg(&g_GX[(size_t)(t*16+b)*2048+jg]);
        }
        __syncthreads();
        if(tid<64){
            int uu=tid>>4,b=tid&15;
            float xi=gs[(0+uu)*16+b], xf=gs[(4+uu)*16+b];
            float xg=gs[(8+uu)*16+b], xo=gs[(12+uu)*16+b];
            float c=cs[uu*16+b];
            float si=1.f/(1.f+expf(-xi)), sf=1.f/(1.f+expf(-xf)), so=1.f/(1.f+expf(-xo));
            float c2=sf*c+si*tanhf(xg);
            float h2=so*tanhf(c2);
            cs[uu*16+b]=c2;
            int unit=u0+uu;
            g_h[b*HH+unit]=h2;
            g_HS[(size_t)(b*TT+t)*HH+unit]=h2;   // b-major: row m == out row
            if(t==TT-1){ out_tail[b*HH+unit]=h2; out_tail[BB*HH+b*HH+unit]=c2; }
        }
        if(t<TT-1){
            __syncthreads();
            if(tid==0){
                __threadfence();
                unsigned a=atomicAdd(&g_bar[0],1u);
                if(a==127u){ atomicExch(&g_bar[0],0u); __threadfence(); atomicAdd(&g_bar[1],1u); }
                else { while(((volatile unsigned*)g_bar)[1]<(unsigned)(t+1)) __nanosleep(40); }
                __threadfence();
            }
            __syncthreads();
        }
    }
}

// ---------------- fp16 mma.sync logits GEMM ----------------
// C[2048,32000] = A16[2048,512] @ B16[32000,512]^T + bias.
// BM=BN=128, BK=32, 256 thr, 8 warps (4m x 2n), warp tile 32x64.
// NOTE: one row = 512 halves = 128 ull (row stride 128, NOT 64).
#define KPAD 40
__global__ __launch_bounds__(256)
void logits_mma_kernel(const float* __restrict__ bias, float* __restrict__ C){
    __shared__ __align__(16) ushortt sA[2][128][KPAD];
    __shared__ __align__(16) ushortt sB[2][128][KPAD];
    const int tid=threadIdx.x, wid=tid>>5, lane=tid&31;
    const int m0=blockIdx.y*128, n0=blockIdx.x*128;
    const int wm=(wid&3)*32, wn=(wid>>2)*64;
    const ull* Ab=(const ull*)g_A16 + (size_t)m0*128;
    const ull* Bb=(const ull*)g_B16 + (size_t)n0*128;
    float acc[2][8][4];
    #pragma unroll
    for(int i=0;i<2;i++)
        #pragma unroll
        for(int j=0;j<8;j++)
            #pragma unroll
            for(int k=0;k<4;k++) acc[i][j][k]=0.f;

    // per K-chunk: 128 rows x 8 ull (32 halves) per matrix = 1024 ull -> 4/thread
    ull pa[4], pb[4];
    auto loadT=[&](int kt){
        #pragma unroll
        for(int i=0;i<4;i++){
            int idx=i*256+tid, r=idx>>3, q=idx&7;
            pa[i]=__ldg(Ab+(size_t)r*128+kt*8+q);
            pb[i]=__ldg(Bb+(size_t)r*128+kt*8+q);
        }
    };
    auto storeT=[&](int s){
        #pragma unroll
        for(int i=0;i<4;i++){
            int idx=i*256+tid, r=idx>>3, q=idx&7;
            *(ull*)&sA[s][r][q*4]=pa[i];
            *(ull*)&sB[s][r][q*4]=pb[i];
        }
    };
    loadT(0); storeT(0); __syncthreads();
    int s=0;
    for(int kt=0;kt<16;kt++){
        if(kt<15) loadT(kt+1);
        #pragma unroll
        for(int k16=0;k16<2;k16++){
            uint32_t af[2][4], bf[8][2];
            #pragma unroll
            for(int mf=0;mf<2;mf++){
                uint32_t addr=s2u(&sA[s][wm+mf*16+(lane&15)][k16*16+(lane>>4)*8]);
                asm volatile("ldmatrix.sync.aligned.m8n8.x4.shared.b16 {%0,%1,%2,%3},[%4];"
                    :"=r"(af[mf][0]),"=r"(af[mf][1]),"=r"(af[mf][2]),"=r"(af[mf][3]):"r"(addr));
            }
            #pragma unroll
            for(int nb=0;nb<4;nb++){
                uint32_t r0,r1,r2,r3;
                uint32_t addr=s2u(&sB[s][wn+nb*16+(lane&15)][k16*16+(lane>>4)*8]);
                asm volatile("ldmatrix.sync.aligned.m8n8.x4.shared.b16 {%0,%1,%2,%3},[%4];"
                    :"=r"(r0),"=r"(r1),"=r"(r2),"=r"(r3):"r"(addr));
                bf[nb*2][0]=r0; bf[nb*2][1]=r2;
                bf[nb*2+1][0]=r1; bf[nb*2+1][1]=r3;
            }
            #pragma unroll
            for(int mf=0;mf<2;mf++)
                #pragma unroll
                for(int nf=0;nf<8;nf++){
                    asm volatile("mma.sync.aligned.m16n8k16.row.col.f32.f16.f16.f32 "
                        "{%0,%1,%2,%3},{%4,%5,%6,%7},{%8,%9},{%0,%1,%2,%3};"
                        :"+f"(acc[mf][nf][0]),"+f"(acc[mf][nf][1]),"+f"(acc[mf][nf][2]),"+f"(acc[mf][nf][3])
                        :"r"(af[mf][0]),"r"(af[mf][1]),"r"(af[mf][2]),"r"(af[mf][3]),
                         "r"(bf[nf][0]),"r"(bf[nf][1]));
                }
        }
        if(kt<15) storeT(s^1);
        __syncthreads();
        s^=1;
    }
    // epilogue: lane r=(lane>>2), c=(lane&3)*2; rows r and r+8
    #pragma unroll
    for(int mf=0;mf<2;mf++){
        int row=m0+wm+mf*16+(lane>>2);
        float* cr0=C+(size_t)row*VV;
        float* cr1=C+(size_t)(row+8)*VV;
        #pragma unroll
        for(int nf=0;nf<8;nf++){
            int col=n0+wn+nf*8+(lane&3)*2;
            float2 bv=__ldg((const float2*)(bias+col));
            float2 v0=make_float2(acc[mf][nf][0]+bv.x, acc[mf][nf][1]+bv.y);
            float2 v1=make_float2(acc[mf][nf][2]+bv.x, acc[mf][nf][3]+bv.y);
            *(float2*)(cr0+col)=v0;
            *(float2*)(cr1+col)=v1;
        }
    }
}

extern "C" void kernel_launch(void* const* d_in,const int* in_sizes,int n_in,
                              void* d_out,int out_size){
    const float* h0   =(const float*)d_in[1];
    const float* c0   =(const float*)d_in[2];
    const void*  tgt  =d_in[3];
    const float* emb  =(const float*)d_in[4];
    const float* W_ih =(const float*)d_in[5];
    const float* W_hh =(const float*)d_in[6];
    const float* b_ih =(const float*)d_in[7];
    const float* b_hh =(const float*)d_in[8];
    const float* W_out=(const float*)d_in[9];
    const float* b_out=(const float*)d_in[10];
    float* out=(float*)d_out;
    void *Xp,*GXp,*biasp;
    cudaGetSymbolAddress(&Xp,g_X);
    cudaGetSymbolAddress(&GXp,g_GX);
    cudaGetSymbolAddress(&biasp,g_bias);
    const int rec_smem=21184*4;
    cudaFuncSetAttribute(recurrence_kernel,cudaFuncAttributeMaxDynamicSharedMemorySize,rec_smem);
    detect_tok_kernel<<<1,256>>>((const unsigned*)tgt);
    prep_bias_kernel<<<G4/256,256>>>(b_ih,b_hh);
    embed_relu_kernel<<<TT*BB,128>>>(tgt,emb);
    convB_kernel<<<16000,256>>>(W_out);
    sgemm_kernel<<<dim3(16,16),256>>>((const float*)Xp,W_ih,(const float*)biasp,(float*)GXp);
    recurrence_kernel<<<128,256,rec_smem>>>(W_hh,h0,c0,out+BTV);
    convA_kernel<<<1024,256>>>();
    logits_mma_kernel<<<dim3(250,16),256>>>(b_out,out);
}

// round 11
// speedup vs baseline: 1.9194x; 1.1238x over previous
#include <cuda_runtime.h>
#include <cuda_fp16.h>
#include <cstdint>
#define BB 16
#define TT 128
#define HH 512
#define G4 2048
#define VV 32000
#define BTV (BB*TT*VV)
#define WPAD 516
typedef unsigned long long ull;
typedef unsigned short ushortt;

__device__ float g_X [TT*BB*HH];
__device__ float g_GX[TT*BB*G4];
__device__ float g_HS[TT*BB*HH];
__device__ float g_h [BB*HH];
__device__ float g_bias[G4];
__device__ volatile unsigned g_flags[128];
__device__ volatile unsigned g_gen;
__device__ int g_tok_is64;
__device__ ushortt g_A16[(size_t)2048*512];
__device__ ushortt g_B16[(size_t)VV*512];

__device__ __forceinline__ ull pack2(float x, float y){ull r;asm("mov.b64 %0,{%1,%2};":"=l"(r):"f"(x),"f"(y));return r;}
__device__ __forceinline__ float2 unpack2(ull v){float2 r;asm("mov.b64 {%0,%1},%2;":"=f"(r.x),"=f"(r.y):"l"(v));return r;}
__device__ __forceinline__ ull fma2(ull a,ull b,ull c){ull d;asm("fma.rn.f32x2 %0,%1,%2,%3;":"=l"(d):"l"(a),"l"(b),"l"(c));return d;}
__device__ __forceinline__ uint32_t s2u(const void* p){
    uint32_t a; asm("{ .reg .u64 t; cvta.to.shared.u64 t,%1; cvt.u32.u64 %0,t; }":"=r"(a):"l"(p)); return a;
}

__global__ void detect_tok_kernel(const unsigned* __restrict__ w){
    __shared__ int any;
    if(threadIdx.x==0) any=0;
    __syncthreads();
    int a=0;
    for(int i=threadIdx.x;i<1024;i+=blockDim.x) a|=(w[2*i+1]!=0u);
    if(a) atomicOr(&any,1);
    __syncthreads();
    if(threadIdx.x==0) g_tok_is64=(any==0)?1:0;
}

__global__ void prep_bias_kernel(const float* __restrict__ bi,const float* __restrict__ bh){
    int i=blockIdx.x*blockDim.x+threadIdx.x;
    if(i<G4) g_bias[i]=bi[i]+bh[i];
    if(i<128) g_flags[i]=0u;
    if(i==0) g_gen=0u;
}

__global__ void embed_relu_kernel(const void* __restrict__ tgt,const float* __restrict__ emb){
    int m=blockIdx.x, t=m>>4, b=m&15;
    long long tok;
    if(t==0) tok=1LL;
    else if(g_tok_is64) tok=((const long long*)tgt)[b*TT+(t-1)];
    else tok=(long long)((const int*)tgt)[b*TT+(t-1)];
    const float4* src=(const float4*)(emb+(size_t)tok*HH);
    float4* dst=(float4*)(g_X+(size_t)m*HH);
    float4 v=__ldg(src+threadIdx.x);
    v.x=fmaxf(v.x,0.f); v.y=fmaxf(v.y,0.f); v.z=fmaxf(v.z,0.f); v.w=fmaxf(v.w,0.f);
    dst[threadIdx.x]=v;
}

// ---- fp16 conversions ----
__device__ __forceinline__ ull pack4h(float4 v){
    ushortt a=__half_as_ushort(__float2half_rn(v.x));
    ushortt b=__half_as_ushort(__float2half_rn(v.y));
    ushortt c=__half_as_ushort(__float2half_rn(v.z));
    ushortt d=__half_as_ushort(__float2half_rn(v.w));
    return (ull)a|((ull)b<<16)|((ull)c<<32)|((ull)d<<48);
}
__global__ void convB_kernel(const float* __restrict__ W){
    size_t i=(size_t)blockIdx.x*blockDim.x+threadIdx.x;
    if(i>=(size_t)VV*128) return;
    float4 v=__ldg((const float4*)W + i);
    ((ull*)g_B16)[i]=pack4h(v);
}
__global__ void convA_kernel(){
    size_t i=(size_t)blockIdx.x*blockDim.x+threadIdx.x;
    if(i>=(size_t)2048*128) return;
    float4 v=*((const float4*)g_HS + i);
    ((ull*)g_A16)[i]=pack4h(v);
}

// C[M,N] = A[M,512] @ Bw[N,512]^T + bias[N]. fp32, used for GX only.
__global__ __launch_bounds__(256,2)
void sgemm_kernel(const float* __restrict__ A,const float* __restrict__ Bw,
                  const float* __restrict__ bias,float* __restrict__ C){
    __shared__ float As[2][16][128];
    __shared__ float Bs[2][16][128];
    const int tid=threadIdx.x, tx=tid&15, ty=tid>>4;
    const int row0=blockIdx.y*128, col0=blockIdx.x*128, q0=tid*2;
    float4 ra[2], rb[2];
    ull acc[8][4];
    #pragma unroll
    for(int mi=0;mi<8;mi++)
        #pragma unroll
        for(int j=0;j<4;j++) acc[mi][j]=0ULL;
    auto loadT=[&](int kt){
        #pragma unroll
        for(int i=0;i<2;i++){
            int q=q0+i, r=q>>2, k4=q&3;
            ra[i]=__ldg((const float4*)(A +(size_t)(row0+r)*512+kt*16+k4*4));
            rb[i]=__ldg((const float4*)(Bw+(size_t)(col0+r)*512+kt*16+k4*4));
        }
    };
    auto storeT=[&](int s){
        #pragma unroll
        for(int i=0;i<2;i++){
            int q=q0+i, r=q>>2, kk=(q&3)*4;
            As[s][kk+0][r]=ra[i].x; As[s][kk+1][r]=ra[i].y;
            As[s][kk+2][r]=ra[i].z; As[s][kk+3][r]=ra[i].w;
            Bs[s][kk+0][r]=rb[i].x; Bs[s][kk+1][r]=rb[i].y;
            Bs[s][kk+2][r]=rb[i].z; Bs[s][kk+3][r]=rb[i].w;
        }
    };
    loadT(0); storeT(0); __syncthreads();
    int s=0;
    for(int kt=0;kt<32;kt++){
        if(kt<31) loadT(kt+1);
        #pragma unroll
        for(int k=0;k<16;k++){
            float4 a0=*(const float4*)&As[s][k][ty*4];
            float4 a1=*(const float4*)&As[s][k][64+ty*4];
            float4 b0=*(const float4*)&Bs[s][k][tx*4];
            float4 b1=*(const float4*)&Bs[s][k][64+tx*4];
            ull bb[4]={pack2(b0.x,b0.y),pack2(b0.z,b0.w),pack2(b1.x,b1.y),pack2(b1.z,b1.w)};
            float av[8]={a0.x,a0.y,a0.z,a0.w,a1.x,a1.y,a1.z,a1.w};
            #pragma unroll
            for(int mi=0;mi<8;mi++){
                ull pa=pack2(av[mi],av[mi]);
                #pragma unroll
                for(int j=0;j<4;j++) acc[mi][j]=fma2(pa,bb[j],acc[mi][j]);
            }
        }
        if(kt<31) storeT(s^1);
        __syncthreads();
        s^=1;
    }
    const int n0=col0+tx*4, n1=col0+64+tx*4;
    float4 bs0=__ldg((const float4*)&bias[n0]);
    float4 bs1=__ldg((const float4*)&bias[n1]);
    #pragma unroll
    for(int mi=0;mi<8;mi++){
        int gm=row0+((mi<4)?(ty*4+mi):(64+ty*4+mi-4));
        size_t ro=(size_t)gm*2048;
        float2 p0=unpack2(acc[mi][0]),p1=unpack2(acc[mi][1]);
        float2 p2=unpack2(acc[mi][2]),p3=unpack2(acc[mi][3]);
        *(float4*)(C+ro+n0)=make_float4(p0.x+bs0.x,p0.y+bs0.y,p1.x+bs0.z,p1.y+bs0.w);
        *(float4*)(C+ro+n1)=make_float4(p2.x+bs1.x,p2.y+bs1.y,p3.x+bs1.z,p3.y+bs1.w);
    }
}

// persistent LSTM recurrence: 128 CTAs x 256 thr, CTA owns 4 hidden units.
// Barrier: distributed flags + master CTA (no same-address atomic pileup).
__global__ __launch_bounds__(256,1)
void recurrence_kernel(const float* __restrict__ W_hh,const float* __restrict__ h0,
                       const float* __restrict__ c0,float* __restrict__ out_tail){
    extern __shared__ float sm[];
    float* Ws=sm;
    float* hb=sm+8256;
    float* part=sm+16512;
    float* gs=sm+20864;
    float* cs=sm+21120;
    const int tid=threadIdx.x, cta=blockIdx.x, u0=cta*4;
    #pragma unroll
    for(int i=0;i<8;i++){
        int q=i*256+tid, r=q>>7, kq=q&127;
        int jr=(r>>2)*512+u0+(r&3);
        float4 w=__ldg((const float4*)W_hh+(size_t)jr*128+kq);
        *(float4*)&Ws[r*WPAD+kq*4]=w;
    }
    if(tid<64){ int uu=tid>>4,b=tid&15; cs[uu*16+b]=c0[b*HH+u0+uu]; }
    __syncthreads();
    const int rq=tid&3, bq=(tid>>2)&3, ks=tid>>4, k0=ks*32;
    for(int t=0;t<TT;t++){
        const float4* hs4=(t==0)?(const float4*)h0:(const float4*)g_h;
        #pragma unroll
        for(int i=0;i<8;i++){
            int q=i*256+tid, b=q>>7, kq=q&127;
            float4 v=__ldcg(hs4+q);
            *(float4*)&hb[b*WPAD+kq*4]=v;
        }
        __syncthreads();
        // packed f32x2 dot: 4 rows x 4 batches per thread, k-chunk of 32
        ull acc2[4][4];
        #pragma unroll
        for(int i=0;i<4;i++)
            #pragma unroll
            for(int j=0;j<4;j++) acc2[i][j]=0ULL;
        const float* wb=&Ws[(4*rq)*WPAD+k0];
        const float* hbb=&hb[(4*bq)*WPAD+k0];
        #pragma unroll
        for(int kk=0;kk<32;kk+=4){
            ull w2[4][2],h2[4][2];
            #pragma unroll
            for(int i=0;i<4;i++){
                w2[i][0]=*(const ull*)(wb+i*WPAD+kk);
                w2[i][1]=*(const ull*)(wb+i*WPAD+kk+2);
            }
            #pragma unroll
            for(int j=0;j<4;j++){
                h2[j][0]=*(const ull*)(hbb+j*WPAD+kk);
                h2[j][1]=*(const ull*)(hbb+j*WPAD+kk+2);
            }
            #pragma unroll
            for(int i=0;i<4;i++)
                #pragma unroll
                for(int j=0;j<4;j++){
                    acc2[i][j]=fma2(w2[i][0],h2[j][0],acc2[i][j]);
                    acc2[i][j]=fma2(w2[i][1],h2[j][1],acc2[i][j]);
                }
        }
        #pragma unroll
        for(int i=0;i<4;i++)
            #pragma unroll
            for(int j=0;j<4;j++){
                float2 p=unpack2(acc2[i][j]);
                part[((4*rq+i)*16+(4*bq+j))*17+ks]=p.x+p.y;
            }
        __syncthreads();
        {
            float ssum=0.f;
            #pragma unroll
            for(int k2=0;k2<16;k2++) ssum+=part[tid*17+k2];
            int r=tid>>4,b=tid&15;
            int jg=(r>>2)*512+u0+(r&3);
            gs[tid]=ssum+__ldg(&g_GX[(size_t)(t*16+b)*2048+jg]);
        }
        __syncthreads();
        if(tid<64){
            int uu=tid>>4,b=tid&15;
            float xi=gs[(0+uu)*16+b], xf=gs[(4+uu)*16+b];
            float xg=gs[(8+uu)*16+b], xo=gs[(12+uu)*16+b];
            float c=cs[uu*16+b];
            float si=1.f/(1.f+expf(-xi)), sf=1.f/(1.f+expf(-xf)), so=1.f/(1.f+expf(-xo));
            float c2=sf*c+si*tanhf(xg);
            float h2v=so*tanhf(c2);
            cs[uu*16+b]=c2;
            int unit=u0+uu;
            g_h[b*HH+unit]=h2v;
            g_HS[(size_t)(b*TT+t)*HH+unit]=h2v;   // b-major: row m == out row
            if(t==TT-1){ out_tail[b*HH+unit]=h2v; out_tail[BB*HH+b*HH+unit]=c2; }
        }
        if(t<TT-1){
            __syncthreads();
            unsigned want=(unsigned)(t+1);
            if(tid==0){ __threadfence(); g_flags[cta]=want; }
            if(cta==0){
                if(tid<128){ while(g_flags[tid]<want) ; }
                __syncthreads();
                if(tid==0){ __threadfence(); g_gen=want; }
            } else {
                if(tid==0){ while(g_gen<want) ; }
            }
            if(tid==0) __threadfence();
            __syncthreads();
        }
    }
}

// ---------------- fp16 mma.sync logits GEMM ----------------
// C[2048,32000] = A16[2048,512] @ B16[32000,512]^T + bias.
// BM=BN=128, BK=32, 256 thr, 8 warps (4m x 2n), warp tile 32x64.
// One row = 512 halves = 128 ull.
#define KPAD 40
__global__ __launch_bounds__(256)
void logits_mma_kernel(const float* __restrict__ bias, float* __restrict__ C){
    __shared__ __align__(16) ushortt sA[2][128][KPAD];
    __shared__ __align__(16) ushortt sB[2][128][KPAD];
    const int tid=threadIdx.x, wid=tid>>5, lane=tid&31;
    const int m0=blockIdx.y*128, n0=blockIdx.x*128;
    const int wm=(wid&3)*32, wn=(wid>>2)*64;
    const ull* Ab=(const ull*)g_A16 + (size_t)m0*128;
    const ull* Bb=(const ull*)g_B16 + (size_t)n0*128;
    float acc[2][8][4];
    #pragma unroll
    for(int i=0;i<2;i++)
        #pragma unroll
        for(int j=0;j<8;j++)
            #pragma unroll
            for(int k=0;k<4;k++) acc[i][j][k]=0.f;
    ull pa[4], pb[4];
    auto loadT=[&](int kt){
        #pragma unroll
        for(int i=0;i<4;i++){
            int idx=i*256+tid, r=idx>>3, q=idx&7;
            pa[i]=__ldg(Ab+(size_t)r*128+kt*8+q);
            pb[i]=__ldg(Bb+(size_t)r*128+kt*8+q);
        }
    };
    auto storeT=[&](int s){
        #pragma unroll
        for(int i=0;i<4;i++){
            int idx=i*256+tid, r=idx>>3, q=idx&7;
            *(ull*)&sA[s][r][q*4]=pa[i];
            *(ull*)&sB[s][r][q*4]=pb[i];
        }
    };
    loadT(0); storeT(0); __syncthreads();
    int s=0;
    for(int kt=0;kt<16;kt++){
        if(kt<15) loadT(kt+1);
        #pragma unroll
        for(int k16=0;k16<2;k16++){
            uint32_t af[2][4], bf[8][2];
            #pragma unroll
            for(int mf=0;mf<2;mf++){
                uint32_t addr=s2u(&sA[s][wm+mf*16+(lane&15)][k16*16+(lane>>4)*8]);
                asm volatile("ldmatrix.sync.aligned.m8n8.x4.shared.b16 {%0,%1,%2,%3},[%4];"
                    :"=r"(af[mf][0]),"=r"(af[mf][1]),"=r"(af[mf][2]),"=r"(af[mf][3]):"r"(addr));
            }
            #pragma unroll
            for(int nb=0;nb<4;nb++){
                uint32_t r0,r1,r2,r3;
                uint32_t addr=s2u(&sB[s][wn+nb*16+(lane&15)][k16*16+(lane>>4)*8]);
                asm volatile("ldmatrix.sync.aligned.m8n8.x4.shared.b16 {%0,%1,%2,%3},[%4];"
                    :"=r"(r0),"=r"(r1),"=r"(r2),"=r"(r3):"r"(addr));
                bf[nb*2][0]=r0; bf[nb*2][1]=r2;
                bf[nb*2+1][0]=r1; bf[nb*2+1][1]=r3;
            }
            #pragma unroll
            for(int mf=0;mf<2;mf++)
                #pragma unroll
                for(int nf=0;nf<8;nf++){
                    asm volatile("mma.sync.aligned.m16n8k16.row.col.f32.f16.f16.f32 "
                        "{%0,%1,%2,%3},{%4,%5,%6,%7},{%8,%9},{%0,%1,%2,%3};"
                        :"+f"(acc[mf][nf][0]),"+f"(acc[mf][nf][1]),"+f"(acc[mf][nf][2]),"+f"(acc[mf][nf][3])
                        :"r"(af[mf][0]),"r"(af[mf][1]),"r"(af[mf][2]),"r"(af[mf][3]),
                         "r"(bf[nf][0]),"r"(bf[nf][1]));
                }
        }
        if(kt<15) storeT(s^1);
        __syncthreads();
        s^=1;
    }
    #pragma unroll
    for(int mf=0;mf<2;mf++){
        int row=m0+wm+mf*16+(lane>>2);
        float* cr0=C+(size_t)row*VV;
        float* cr1=C+(size_t)(row+8)*VV;
        #pragma unroll
        for(int nf=0;nf<8;nf++){
            int col=n0+wn+nf*8+(lane&3)*2;
            float2 bv=__ldg((const float2*)(bias+col));
            float2 v0=make_float2(acc[mf][nf][0]+bv.x, acc[mf][nf][1]+bv.y);
            float2 v1=make_float2(acc[mf][nf][2]+bv.x, acc[mf][nf][3]+bv.y);
            *(float2*)(cr0+col)=v0;
            *(float2*)(cr1+col)=v1;
        }
    }
}

extern "C" void kernel_launch(void* const* d_in,const int* in_sizes,int n_in,
                              void* d_out,int out_size){
    const float* h0   =(const float*)d_in[1];
    const float* c0   =(const float*)d_in[2];
    const void*  tgt  =d_in[3];
    const float* emb  =(const float*)d_in[4];
    const float* W_ih =(const float*)d_in[5];
    const float* W_hh =(const float*)d_in[6];
    const float* b_ih =(const float*)d_in[7];
    const float* b_hh =(const float*)d_in[8];
    const float* W_out=(const float*)d_in[9];
    const float* b_out=(const float*)d_in[10];
    float* out=(float*)d_out;
    void *Xp,*GXp,*biasp;
    cudaGetSymbolAddress(&Xp,g_X);
    cudaGetSymbolAddress(&GXp,g_GX);
    cudaGetSymbolAddress(&biasp,g_bias);
    const int rec_smem=21184*4;
    cudaFuncSetAttribute(recurrence_kernel,cudaFuncAttributeMaxDynamicSharedMemorySize,rec_smem);
    detect_tok_kernel<<<1,256>>>((const unsigned*)tgt);
    prep_bias_kernel<<<G4/256,256>>>(b_ih,b_hh);
    embed_relu_kernel<<<TT*BB,128>>>(tgt,emb);
    convB_kernel<<<16000,256>>>(W_out);
    sgemm_kernel<<<dim3(16,16),256>>>((const float*)Xp,W_ih,(const float*)biasp,(float*)GXp);
    recurrence_kernel<<<128,256,rec_smem>>>(W_hh,h0,c0,out+BTV);
    convA_kernel<<<1024,256>>>();
    logits_mma_kernel<<<dim3(250,16),256>>>(b_out,out);
}

// round 12
// speedup vs baseline: 1.9457x; 1.0137x over previous
#include <cuda_runtime.h>
#include <cuda_fp16.h>
#include <cstdint>
#define BB 16
#define TT 128
#define HH 512
#define G4 2048
#define VV 32000
#define BTV (BB*TT*VV)
#define WPAD 516
typedef unsigned long long ull;
typedef unsigned short ushortt;

__device__ float g_X [TT*BB*HH];
__device__ float g_GX[TT*BB*G4];
__device__ float g_HS[TT*BB*HH];
__device__ float g_h [BB*HH];
__device__ float g_bias[G4];
__device__ volatile unsigned g_flags[128];
__device__ volatile unsigned g_gen;
__device__ int g_tok_is64;
__device__ ushortt g_A16[(size_t)2048*512];
__device__ ushortt g_B16[(size_t)VV*512];

__device__ __forceinline__ ull pack2(float x, float y){ull r;asm("mov.b64 %0,{%1,%2};":"=l"(r):"f"(x),"f"(y));return r;}
__device__ __forceinline__ float2 unpack2(ull v){float2 r;asm("mov.b64 {%0,%1},%2;":"=f"(r.x),"=f"(r.y):"l"(v));return r;}
__device__ __forceinline__ ull fma2(ull a,ull b,ull c){ull d;asm("fma.rn.f32x2 %0,%1,%2,%3;":"=l"(d):"l"(a),"l"(b),"l"(c));return d;}
__device__ __forceinline__ uint32_t s2u(const void* p){
    uint32_t a; asm("{ .reg .u64 t; cvta.to.shared.u64 t,%1; cvt.u32.u64 %0,t; }":"=r"(a):"l"(p)); return a;
}
__device__ __forceinline__ void cpa16(uint32_t dst, const void* src){
    asm volatile("cp.async.cg.shared.global [%0],[%1],16;"::"r"(dst),"l"(src):"memory");
}
__device__ __forceinline__ void cp_commit(){ asm volatile("cp.async.commit_group;":::"memory"); }
template<int N> __device__ __forceinline__ void cp_wait(){ asm volatile("cp.async.wait_group %0;"::"n"(N):"memory"); }

// prep: bias+flags (blocks 0..7), token dtype detect (block 8)
__global__ void prep_kernel(const float* __restrict__ bi,const float* __restrict__ bh,
                            const unsigned* __restrict__ w){
    if(blockIdx.x<8){
        int i=blockIdx.x*256+threadIdx.x;
        g_bias[i]=bi[i]+bh[i];
        if(i<128) g_flags[i]=0u;
        if(i==0) g_gen=0u;
    } else {
        __shared__ int any;
        if(threadIdx.x==0) any=0;
        __syncthreads();
        int a=0;
        for(int i=threadIdx.x;i<1024;i+=blockDim.x) a|=(w[2*i+1]!=0u);
        if(a) atomicOr(&any,1);
        __syncthreads();
        if(threadIdx.x==0) g_tok_is64=(any==0)?1:0;
    }
}

__global__ void embed_relu_kernel(const void* __restrict__ tgt,const float* __restrict__ emb){
    int m=blockIdx.x, t=m>>4, b=m&15;
    long long tok;
    if(t==0) tok=1LL;
    else if(g_tok_is64) tok=((const long long*)tgt)[b*TT+(t-1)];
    else tok=(long long)((const int*)tgt)[b*TT+(t-1)];
    const float4* src=(const float4*)(emb+(size_t)tok*HH);
    float4* dst=(float4*)(g_X+(size_t)m*HH);
    float4 v=__ldg(src+threadIdx.x);
    v.x=fmaxf(v.x,0.f); v.y=fmaxf(v.y,0.f); v.z=fmaxf(v.z,0.f); v.w=fmaxf(v.w,0.f);
    dst[threadIdx.x]=v;
}

// ---- fp16 conversions ----
__device__ __forceinline__ ull pack4h(float4 v){
    ushortt a=__half_as_ushort(__float2half_rn(v.x));
    ushortt b=__half_as_ushort(__float2half_rn(v.y));
    ushortt c=__half_as_ushort(__float2half_rn(v.z));
    ushortt d=__half_as_ushort(__float2half_rn(v.w));
    return (ull)a|((ull)b<<16)|((ull)c<<32)|((ull)d<<48);
}
__global__ void convB_kernel(const float* __restrict__ W){
    size_t i=(size_t)blockIdx.x*blockDim.x+threadIdx.x;
    if(i>=(size_t)VV*128) return;
    float4 v=__ldg((const float4*)W + i);
    ((ull*)g_B16)[i]=pack4h(v);
}
__global__ void convA_kernel(){
    size_t i=(size_t)blockIdx.x*blockDim.x+threadIdx.x;
    if(i>=(size_t)2048*128) return;
    float4 v=*((const float4*)g_HS + i);
    ((ull*)g_A16)[i]=pack4h(v);
}

// C[M,N] = A[M,512] @ Bw[N,512]^T + bias[N]. fp32, used for GX only.
__global__ __launch_bounds__(256,2)
void sgemm_kernel(const float* __restrict__ A,const float* __restrict__ Bw,
                  const float* __restrict__ bias,float* __restrict__ C){
    __shared__ float As[2][16][128];
    __shared__ float Bs[2][16][128];
    const int tid=threadIdx.x, tx=tid&15, ty=tid>>4;
    const int row0=blockIdx.y*128, col0=blockIdx.x*128, q0=tid*2;
    float4 ra[2], rb[2];
    ull acc[8][4];
    #pragma unroll
    for(int mi=0;mi<8;mi++)
        #pragma unroll
        for(int j=0;j<4;j++) acc[mi][j]=0ULL;
    auto loadT=[&](int kt){
        #pragma unroll
        for(int i=0;i<2;i++){
            int q=q0+i, r=q>>2, k4=q&3;
            ra[i]=__ldg((const float4*)(A +(size_t)(row0+r)*512+kt*16+k4*4));
            rb[i]=__ldg((const float4*)(Bw+(size_t)(col0+r)*512+kt*16+k4*4));
        }
    };
    auto storeT=[&](int s){
        #pragma unroll
        for(int i=0;i<2;i++){
            int q=q0+i, r=q>>2, kk=(q&3)*4;
            As[s][kk+0][r]=ra[i].x; As[s][kk+1][r]=ra[i].y;
            As[s][kk+2][r]=ra[i].z; As[s][kk+3][r]=ra[i].w;
            Bs[s][kk+0][r]=rb[i].x; Bs[s][kk+1][r]=rb[i].y;
            Bs[s][kk+2][r]=rb[i].z; Bs[s][kk+3][r]=rb[i].w;
        }
    };
    loadT(0); storeT(0); __syncthreads();
    int s=0;
    for(int kt=0;kt<32;kt++){
        if(kt<31) loadT(kt+1);
        #pragma unroll
        for(int k=0;k<16;k++){
            float4 a0=*(const float4*)&As[s][k][ty*4];
            float4 a1=*(const float4*)&As[s][k][64+ty*4];
            float4 b0=*(const float4*)&Bs[s][k][tx*4];
            float4 b1=*(const float4*)&Bs[s][k][64+tx*4];
            ull bb[4]={pack2(b0.x,b0.y),pack2(b0.z,b0.w),pack2(b1.x,b1.y),pack2(b1.z,b1.w)};
            float av[8]={a0.x,a0.y,a0.z,a0.w,a1.x,a1.y,a1.z,a1.w};
            #pragma unroll
            for(int mi=0;mi<8;mi++){
                ull pa=pack2(av[mi],av[mi]);
                #pragma unroll
                for(int j=0;j<4;j++) acc[mi][j]=fma2(pa,bb[j],acc[mi][j]);
            }
        }
        if(kt<31) storeT(s^1);
        __syncthreads();
        s^=1;
    }
    const int n0=col0+tx*4, n1=col0+64+tx*4;
    float4 bs0=__ldg((const float4*)&bias[n0]);
    float4 bs1=__ldg((const float4*)&bias[n1]);
    #pragma unroll
    for(int mi=0;mi<8;mi++){
        int gm=row0+((mi<4)?(ty*4+mi):(64+ty*4+mi-4));
        size_t ro=(size_t)gm*2048;
        float2 p0=unpack2(acc[mi][0]),p1=unpack2(acc[mi][1]);
        float2 p2=unpack2(acc[mi][2]),p3=unpack2(acc[mi][3]);
        *(float4*)(C+ro+n0)=make_float4(p0.x+bs0.x,p0.y+bs0.y,p1.x+bs0.z,p1.y+bs0.w);
        *(float4*)(C+ro+n1)=make_float4(p2.x+bs1.x,p2.y+bs1.y,p3.x+bs1.z,p3.y+bs1.w);
    }
}

// persistent LSTM recurrence: 128 CTAs x 256 thr, CTA owns 4 hidden units.
__global__ __launch_bounds__(256,1)
void recurrence_kernel(const float* __restrict__ W_hh,const float* __restrict__ h0,
                       const float* __restrict__ c0,float* __restrict__ out_tail){
    extern __shared__ float sm[];
    float* Ws=sm;
    float* hb=sm+8256;
    float* part=sm+16512;
    float* gs=sm+20864;
    float* cs=sm+21120;
    const int tid=threadIdx.x, cta=blockIdx.x, u0=cta*4;
    #pragma unroll
    for(int i=0;i<8;i++){
        int q=i*256+tid, r=q>>7, kq=q&127;
        int jr=(r>>2)*512+u0+(r&3);
        float4 w=__ldg((const float4*)W_hh+(size_t)jr*128+kq);
        *(float4*)&Ws[r*WPAD+kq*4]=w;
    }
    if(tid<64){ int uu=tid>>4,b=tid&15; cs[uu*16+b]=c0[b*HH+u0+uu]; }
    __syncthreads();
    const int rq=tid&3, bq=(tid>>2)&3, ks=tid>>4, k0=ks*32;
    for(int t=0;t<TT;t++){
        const float4* hs4=(t==0)?(const float4*)h0:(const float4*)g_h;
        #pragma unroll
        for(int i=0;i<8;i++){
            int q=i*256+tid, b=q>>7, kq=q&127;
            float4 v=__ldcg(hs4+q);
            *(float4*)&hb[b*WPAD+kq*4]=v;
        }
        __syncthreads();
        ull acc2[4][4];
        #pragma unroll
        for(int i=0;i<4;i++)
            #pragma unroll
            for(int j=0;j<4;j++) acc2[i][j]=0ULL;
        const float* wb=&Ws[(4*rq)*WPAD+k0];
        const float* hbb=&hb[(4*bq)*WPAD+k0];
        #pragma unroll
        for(int kk=0;kk<32;kk+=4){
            ull w2[4][2],h2[4][2];
            #pragma unroll
            for(int i=0;i<4;i++){
                w2[i][0]=*(const ull*)(wb+i*WPAD+kk);
                w2[i][1]=*(const ull*)(wb+i*WPAD+kk+2);
            }
            #pragma unroll
            for(int j=0;j<4;j++){
                h2[j][0]=*(const ull*)(hbb+j*WPAD+kk);
                h2[j][1]=*(const ull*)(hbb+j*WPAD+kk+2);
            }
            #pragma unroll
            for(int i=0;i<4;i++)
                #pragma unroll
                for(int j=0;j<4;j++){
                    acc2[i][j]=fma2(w2[i][0],h2[j][0],acc2[i][j]);
                    acc2[i][j]=fma2(w2[i][1],h2[j][1],acc2[i][j]);
                }
        }
        #pragma unroll
        for(int i=0;i<4;i++)
            #pragma unroll
            for(int j=0;j<4;j++){
                float2 p=unpack2(acc2[i][j]);
                part[((4*rq+i)*16+(4*bq+j))*17+ks]=p.x+p.y;
            }
        __syncthreads();
        {
            float ssum=0.f;
            #pragma unroll
            for(int k2=0;k2<16;k2++) ssum+=part[tid*17+k2];
            int r=tid>>4,b=tid&15;
            int jg=(r>>2)*512+u0+(r&3);
            gs[tid]=ssum+__ldg(&g_GX[(size_t)(t*16+b)*2048+jg]);
        }
        __syncthreads();
        if(tid<64){
            int uu=tid>>4,b=tid&15;
            float xi=gs[(0+uu)*16+b], xf=gs[(4+uu)*16+b];
            float xg=gs[(8+uu)*16+b], xo=gs[(12+uu)*16+b];
            float c=cs[uu*16+b];
            float si=1.f/(1.f+expf(-xi)), sf=1.f/(1.f+expf(-xf)), so=1.f/(1.f+expf(-xo));
            float c2=sf*c+si*tanhf(xg);
            float h2v=so*tanhf(c2);
            cs[uu*16+b]=c2;
            int unit=u0+uu;
            g_h[b*HH+unit]=h2v;
            g_HS[(size_t)(b*TT+t)*HH+unit]=h2v;
            if(t==TT-1){ out_tail[b*HH+unit]=h2v; out_tail[BB*HH+b*HH+unit]=c2; }
        }
        if(t<TT-1){
            __syncthreads();
            unsigned want=(unsigned)(t+1);
            if(tid==0){ __threadfence(); g_flags[cta]=want; }
            if(cta==0){
                if(tid<128){ while(g_flags[tid]<want) ; }
                __syncthreads();
                if(tid==0){ __threadfence(); g_gen=want; }
            } else {
                if(tid==0){ while(g_gen<want) ; }
            }
            if(tid==0) __threadfence();
            __syncthreads();
        }
    }
}

// ---------------- fp16 mma.sync logits GEMM, cp.async 3-stage ----------------
// C[2048,32000] = A16[2048,512] @ B16[32000,512]^T + bias.
// BM=BN=128, BK=32, 256 thr, 8 warps (4m x 2n), warp tile 32x64. One row = 1024 B.
#define KPAD 40
#define STG_H (128*KPAD)            // halves per stage per matrix
#define LOG_SMEM (3*STG_H*2*2)      // 61440 bytes
__global__ __launch_bounds__(256,2)
void logits_mma_kernel(const float* __restrict__ bias, float* __restrict__ C){
    extern __shared__ ushortt dyn[];
    ushortt* sA=dyn;                // [3][128][KPAD]
    ushortt* sB=dyn+3*STG_H;
    const int tid=threadIdx.x, wid=tid>>5, lane=tid&31;
    const int m0=blockIdx.y*128, n0=blockIdx.x*128;
    const int wm=(wid&3)*32, wn=(wid>>2)*64;
    const char* Ab=(const char*)g_A16 + (size_t)m0*1024;
    const char* Bb=(const char*)g_B16 + (size_t)n0*1024;
    const uint32_t sAu=s2u(sA), sBu=s2u(sB);
    float acc[2][8][4];
    #pragma unroll
    for(int i=0;i<2;i++)
        #pragma unroll
        for(int j=0;j<8;j++)
            #pragma unroll
            for(int k=0;k<4;k++) acc[i][j][k]=0.f;

    // per chunk per matrix: 128 rows x 64B = 512 x 16B ops -> 2/thread
    auto issue=[&](int c){
        int st=c%3;
        #pragma unroll
        for(int i=0;i<2;i++){
            int idx=i*256+tid, r=idx>>2, q=idx&3;
            uint32_t so=(uint32_t)(st*STG_H*2 + r*(KPAD*2) + q*16);
            const char* gsrc=Ab + (size_t)r*1024 + c*64 + q*16;
            cpa16(sAu+so, gsrc);
            cpa16(sBu+so, Bb + (size_t)r*1024 + c*64 + q*16);
        }
        cp_commit();
    };
    auto compute=[&](int st){
        const ushortt* A_=sA+st*STG_H;
        const ushortt* B_=sB+st*STG_H;
        #pragma unroll
        for(int k16=0;k16<2;k16++){
            uint32_t af[2][4], bf[8][2];
            #pragma unroll
            for(int mf=0;mf<2;mf++){
                uint32_t addr=s2u(&A_[(wm+mf*16+(lane&15))*KPAD + k16*16+(lane>>4)*8]);
                asm volatile("ldmatrix.sync.aligned.m8n8.x4.shared.b16 {%0,%1,%2,%3},[%4];"
                    :"=r"(af[mf][0]),"=r"(af[mf][1]),"=r"(af[mf][2]),"=r"(af[mf][3]):"r"(addr));
            }
            #pragma unroll
            for(int nb=0;nb<4;nb++){
                uint32_t r0,r1,r2,r3;
                uint32_t addr=s2u(&B_[(wn+nb*16+(lane&15))*KPAD + k16*16+(lane>>4)*8]);
                asm volatile("ldmatrix.sync.aligned.m8n8.x4.shared.b16 {%0,%1,%2,%3},[%4];"
                    :"=r"(r0),"=r"(r1),"=r"(r2),"=r"(r3):"r"(addr));
                bf[nb*2][0]=r0; bf[nb*2][1]=r2;
                bf[nb*2+1][0]=r1; bf[nb*2+1][1]=r3;
            }
            #pragma unroll
            for(int mf=0;mf<2;mf++)
                #pragma unroll
                for(int nf=0;nf<8;nf++){
                    asm volatile("mma.sync.aligned.m16n8k16.row.col.f32.f16.f16.f32 "
                        "{%0,%1,%2,%3},{%4,%5,%6,%7},{%8,%9},{%0,%1,%2,%3};"
                        :"+f"(acc[mf][nf][0]),"+f"(acc[mf][nf][1]),"+f"(acc[mf][nf][2]),"+f"(acc[mf][nf][3])
                        :"r"(af[mf][0]),"r"(af[mf][1]),"r"(af[mf][2]),"r"(af[mf][3]),
                         "r"(bf[nf][0]),"r"(bf[nf][1]));
                }
        }
    };

    issue(0); issue(1); issue(2);
    for(int kt=0;kt<14;kt++){
        cp_wait<2>();
        __syncthreads();
        compute(kt%3);
        __syncthreads();
        if(kt<13) issue(kt+3);
    }
    cp_wait<1>(); __syncthreads(); compute(14%3); __syncthreads();
    cp_wait<0>(); __syncthreads(); compute(15%3);

    #pragma unroll
    for(int mf=0;mf<2;mf++){
        int row=m0+wm+mf*16+(lane>>2);
        float* cr0=C+(size_t)row*VV;
        float* cr1=C+(size_t)(row+8)*VV;
        #pragma unroll
        for(int nf=0;nf<8;nf++){
            int col=n0+wn+nf*8+(lane&3)*2;
            float2 bv=__ldg((const float2*)(bias+col));
            float2 v0=make_float2(acc[mf][nf][0]+bv.x, acc[mf][nf][1]+bv.y);
            float2 v1=make_float2(acc[mf][nf][2]+bv.x, acc[mf][nf][3]+bv.y);
            *(float2*)(cr0+col)=v0;
            *(float2*)(cr1+col)=v1;
        }
    }
}

extern "C" void kernel_launch(void* const* d_in,const int* in_sizes,int n_in,
                              void* d_out,int out_size){
    const float* h0   =(const float*)d_in[1];
    const float* c0   =(const float*)d_in[2];
    const void*  tgt  =d_in[3];
    const float* emb  =(const float*)d_in[4];
    const float* W_ih =(const float*)d_in[5];
    const float* W_hh =(const float*)d_in[6];
    const float* b_ih =(const float*)d_in[7];
    const float* b_hh =(const float*)d_in[8];
    const float* W_out=(const float*)d_in[9];
    const float* b_out=(const float*)d_in[10];
    float* out=(float*)d_out;
    void *Xp,*GXp,*biasp;
    cudaGetSymbolAddress(&Xp,g_X);
    cudaGetSymbolAddress(&GXp,g_GX);
    cudaGetSymbolAddress(&biasp,g_bias);
    const int rec_smem=21184*4;
    cudaFuncSetAttribute(recurrence_kernel,cudaFuncAttributeMaxDynamicSharedMemorySize,rec_smem);
    cudaFuncSetAttribute(logits_mma_kernel,cudaFuncAttributeMaxDynamicSharedMemorySize,LOG_SMEM);
    prep_kernel<<<9,256>>>(b_ih,b_hh,(const unsigned*)tgt);
    embed_relu_kernel<<<TT*BB,128>>>(tgt,emb);
    sgemm_kernel<<<dim3(16,16),256>>>((const float*)Xp,W_ih,(const float*)biasp,(float*)GXp);
    recurrence_kernel<<<128,256,rec_smem>>>(W_hh,h0,c0,out+BTV);
    convB_kernel<<<16000,256>>>(W_out);
    convA_kernel<<<1024,256>>>();
    logits_mma_kernel<<<dim3(250,16),256,LOG_SMEM>>>(b_out,out);
}